// round 9
// baseline (speedup 1.0000x reference)
#include <cuda_runtime.h>
#include <cstdint>

#define DMV  16
#define TILE 256

// Packed per-l constants, 112 floats:
//  [0:16) G1 col-major {1,2,4,8} | [16:64) G2 col-major pad8 {3,5,6,9,10,12}
//  [64:80) G3 {7,11,13,14} | [80:90) bc | [96:106) b0
__device__ float d_P[32][112];

__device__ __forceinline__ float cayley_sign(int a, int b) {
    if (a & b & 8) return 0.0f;            // e3 * e3 = 0
    int s = 0;
    for (int t = a >> 1; t; t >>= 1) s += __popc(t & b);
    return (s & 1) ? -1.0f : 1.0f;
}
__device__ __forceinline__ uint32_t smem_u32(const void* p) {
    return (uint32_t)__cvta_generic_to_shared(p);
}
__device__ __forceinline__ void cp_async16(uint32_t s, const void* g) {
    asm volatile("cp.async.cg.shared.global [%0], [%1], 16;" :: "r"(s), "l"(g));
}
__device__ __forceinline__ float4 shfl_xor4(float4 v, int m) {
    v.x = __shfl_xor_sync(0xFFFFFFFFu, v.x, m);
    v.y = __shfl_xor_sync(0xFFFFFFFFu, v.y, m);
    v.z = __shfl_xor_sync(0xFFFFFFFFu, v.z, m);
    v.w = __shfl_xor_sync(0xFFFFFFFFu, v.w, m);
    return v;
}

// ---------------------------------------------------------------------------
// Setup: ONE block, 1024 threads. All 32 l's Taylor exps run in parallel on
// 16 warps (two 16-lane groups each, width-16 shuffles). Then Sb + packing.
// ---------------------------------------------------------------------------
__global__ void __launch_bounds__(1024)
setup_kernel(const float* __restrict__ instr,
             const float* __restrict__ remap,   // [4,10,10]
             const float* __restrict__ selw,    // [4,2]
             const float* __restrict__ selb)    // [4]
{
    __shared__ float sgn[256];
    __shared__ float Mv[32][16], Mre[32][16], wv[32][4];
    __shared__ float Sb[32][256];

    const int tid  = threadIdx.x;
    const int w    = tid >> 5;
    const int lane = tid & 31;

    if (tid < 256) sgn[tid] = cayley_sign(tid >> 4, tid & 15);
    __syncthreads();

    if (w < 16) {                       // Taylor exp, 2 l per warp
        const int l  = 2 * w + (lane >> 4);
        const int sl = lane & 15;
        float xv   = (__popc(sl) == 2) ? -0.5f * instr[l * DMV + sl] : 0.0f;
        float term = (sl == 0) ? 1.0f : 0.0f;
        float acc  = term;
        for (int n = 1; n < 16; n++) {
            float nt = 0.0f;
            #pragma unroll
            for (int aa = 0; aa < 16; aa++) {
                float ta = __shfl_sync(0xFFFFFFFFu, term, aa, 16);
                float xa = __shfl_sync(0xFFFFFFFFu, xv, aa ^ sl, 16);
                nt += ta * xa * sgn[aa * 16 + (aa ^ sl)];
            }
            term = nt / (float)n;
            acc += term;
        }
        Mv[l][sl] = acc;
        int g = __popc(sl);
        Mre[l][sl] = acc * ((((g * (g - 1) / 2) & 1) != 0) ? -1.0f : 1.0f);
    } else if (w == 16) {               // selector softmax, 1 l per lane
        const int l = lane;
        float s0 = instr[l * DMV + 0], s1 = instr[l * DMV + 15];
        float lg[4], m = -3.4e38f;
        #pragma unroll
        for (int k = 0; k < 4; k++) {
            lg[k] = fmaf(s0, selw[k * 2], fmaf(s1, selw[k * 2 + 1], selb[k]));
            m = fmaxf(m, lg[k]);
        }
        float sum = 0.0f;
        #pragma unroll
        for (int k = 0; k < 4; k++) { lg[k] = expf(lg[k] - m); sum += lg[k]; }
        #pragma unroll
        for (int k = 0; k < 4; k++) wv[l][k] = lg[k] / sum;
    }
    __syncthreads();

    // Sb[l][a*16+b] = sum_i Lm[a][i]*Rm[i][b]; 8 entries per thread
    #pragma unroll
    for (int rep = 0; rep < 8; rep++) {
        int idx = rep * 1024 + tid;     // 32*256 = 8192
        int l = idx >> 8, ab = idx & 255, a = ab >> 4, b = ab & 15;
        float s = 0.0f;
        #pragma unroll
        for (int i = 0; i < 16; i++)
            s += Mv[l][a ^ i] * sgn[(a ^ i) * 16 + a]
               * Mre[l][i ^ b] * sgn[i * 16 + (i ^ b)];
        Sb[l][ab] = s;
    }
    __syncthreads();

    const int g1[4] = {1, 2, 4, 8};
    const int g2[6] = {3, 5, 6, 9, 10, 12};
    const int g3[4] = {7, 11, 13, 14};

    for (int idx = tid; idx < 32 * 112; idx += 1024) {
        int l = idx / 112, p = idx % 112;
        float val = 0.0f;
        if (p < 16) {
            int j = p >> 2, i = p & 3;
            val = Sb[l][g1[j] * 16 + g1[i]];
        } else if (p < 64) {
            int t = p - 16, j = t >> 3, i = t & 7;
            val = (i < 6) ? Sb[l][g2[j] * 16 + g2[i]] : 0.0f;
        } else if (p < 80) {
            int t = p - 64, j = t >> 2, i = t & 3;
            val = Sb[l][g3[j] * 16 + g3[i]];
        } else if (p >= 80 && p < 90) {
            int i = p - 80;
            #pragma unroll
            for (int k = 0; k < 4; k++) {
                const float* tab = remap + k * 100 + i * 10;
                float rowc = 0.0f;
                #pragma unroll
                for (int j = 0; j < 10; j++) rowc += tab[j] * (float)j;
                val += wv[l][k] * rowc;
            }
        } else if (p >= 96 && p < 106) {
            int i = p - 96;
            #pragma unroll
            for (int k = 0; k < 4; k++)
                val += wv[l][k] * remap[k * 100 + i * 10];
        }
        d_P[l][p] = val;
    }
}

// ---------------------------------------------------------------------------
// Main kernel: one tile (256 rows) per block. cp.async coalesced stage-in ->
// swizzled SMEM; thread t computes row rr = 64*(t&3)+(t>>2); outputs leave
// via a 4x4 register butterfly transpose -> coalesced streaming STG.
// Swizzle sw(r) = ((r>>1)^(r>>6))&3: conflict-free for the staging writes AND
// the permuted compute reads (rows {i,64+i,128+i,192+i} get distinct cols).
// ---------------------------------------------------------------------------
__global__ void __launch_bounds__(256, 5)
sandwich_color_kernel(const float* __restrict__ state,
                      float* __restrict__ out,
                      int N)
{
    __shared__ __align__(16) float4 buf[TILE * 4];   // 16 KB
    __shared__ __align__(16) float P[112];

    const int l     = blockIdx.y;
    const int tid   = threadIdx.x;
    const int tile0 = blockIdx.x * TILE;
    const int nvalid = min(TILE, N - tile0);

    if (tid < 112) P[tid] = d_P[l][tid];

    const size_t gbase4 = ((size_t)l * N + tile0) * 4;
    const float4* gin  = reinterpret_cast<const float4*>(state) + gbase4;
    float4*       gout = reinterpret_cast<float4*>(out)   + gbase4;

    // stage in: coalesced cp.async -> swizzled SMEM
    #pragma unroll
    for (int k = 0; k < 4; k++) {
        int e = k * 256 + tid;
        int r = e >> 2, c = e & 3;
        if (r < nvalid) {
            int sw = ((r >> 1) ^ (r >> 6)) & 3;
            cp_async16(smem_u32(&buf[r * 4 + (c ^ sw)]), gin + e);
        }
    }
    asm volatile("cp.async.commit_group;");
    asm volatile("cp.async.wait_group 0;" ::: "memory");
    __syncthreads();

    const int c  = tid & 3;
    const int i  = tid >> 2;
    const int rr = 64 * c + i;                    // this thread's row
    const int sw = ((rr >> 1) ^ (rr >> 6)) & 3;

    float4 v0 = buf[rr * 4 + (0 ^ sw)];
    float4 v1 = buf[rr * 4 + (1 ^ sw)];
    float4 v2 = buf[rr * 4 + (2 ^ sw)];
    float4 v3 = buf[rr * 4 + (3 ^ sw)];

    const float x0 = v0.x, x1 = v0.y, x2  = v0.z, x3  = v0.w;
    const float x4 = v1.x, x5 = v1.y, x6  = v1.z, x7  = v1.w;
    const float x8 = v2.x, x9 = v2.y, x10 = v2.z, x11 = v2.w;
    const float x12 = v3.x, x13 = v3.y, x14 = v3.z;   // x15 unused

    const float4* P4 = reinterpret_cast<const float4*>(P);

    // grade-1 block
    float4 a0 = P4[0], a1 = P4[1], a2 = P4[2], a3 = P4[3];
    float y1 = fmaf(x8, a3.x, fmaf(x4, a2.x, fmaf(x2, a1.x, x1 * a0.x)));
    float y2 = fmaf(x8, a3.y, fmaf(x4, a2.y, fmaf(x2, a1.y, x1 * a0.y)));
    float y4 = fmaf(x8, a3.z, fmaf(x4, a2.z, fmaf(x2, a1.z, x1 * a0.z)));
    float y8 = fmaf(x8, a3.w, fmaf(x4, a2.w, fmaf(x2, a1.w, x1 * a0.w)));

    // grade-2 block
    float y3, y5, y6, y9, y10, y12;
    {
        float4 cA = P4[4], cB = P4[5];
        y3 = x3 * cA.x; y5 = x3 * cA.y; y6  = x3 * cA.z;
        y9 = x3 * cA.w; y10 = x3 * cB.x; y12 = x3 * cB.y;
    }
    {
        float4 cA = P4[6], cB = P4[7];
        y3 = fmaf(x5, cA.x, y3); y5  = fmaf(x5, cA.y, y5);  y6  = fmaf(x5, cA.z, y6);
        y9 = fmaf(x5, cA.w, y9); y10 = fmaf(x5, cB.x, y10); y12 = fmaf(x5, cB.y, y12);
    }
    {
        float4 cA = P4[8], cB = P4[9];
        y3 = fmaf(x6, cA.x, y3); y5  = fmaf(x6, cA.y, y5);  y6  = fmaf(x6, cA.z, y6);
        y9 = fmaf(x6, cA.w, y9); y10 = fmaf(x6, cB.x, y10); y12 = fmaf(x6, cB.y, y12);
    }
    {
        float4 cA = P4[10], cB = P4[11];
        y3 = fmaf(x9, cA.x, y3); y5  = fmaf(x9, cA.y, y5);  y6  = fmaf(x9, cA.z, y6);
        y9 = fmaf(x9, cA.w, y9); y10 = fmaf(x9, cB.x, y10); y12 = fmaf(x9, cB.y, y12);
    }
    {
        float4 cA = P4[12], cB = P4[13];
        y3 = fmaf(x10, cA.x, y3); y5  = fmaf(x10, cA.y, y5);  y6  = fmaf(x10, cA.z, y6);
        y9 = fmaf(x10, cA.w, y9); y10 = fmaf(x10, cB.x, y10); y12 = fmaf(x10, cB.y, y12);
    }
    {
        float4 cA = P4[14], cB = P4[15];
        y3 = fmaf(x12, cA.x, y3); y5  = fmaf(x12, cA.y, y5);  y6  = fmaf(x12, cA.z, y6);
        y9 = fmaf(x12, cA.w, y9); y10 = fmaf(x12, cB.x, y10); y12 = fmaf(x12, cB.y, y12);
    }

    // grade-3 block
    float4 h0 = P4[16], h1 = P4[17], h2 = P4[18], h3 = P4[19];
    float y7  = fmaf(x14, h3.x, fmaf(x13, h2.x, fmaf(x11, h1.x, x7 * h0.x)));
    float y11 = fmaf(x14, h3.y, fmaf(x13, h2.y, fmaf(x11, h1.y, x7 * h0.y)));
    float y13 = fmaf(x14, h3.z, fmaf(x13, h2.z, fmaf(x11, h1.z, x7 * h0.z)));
    float y14 = fmaf(x14, h3.w, fmaf(x13, h2.w, fmaf(x11, h1.w, x7 * h0.w)));

    // color unit from x0 (y0 == x0: M~M = 1, grade preserved)
    float raw = x0 * 9.0f;
    float cc = fminf(fmaxf(rintf(raw), 0.0f), 9.0f);
    float dm = raw - cc;
    float m = -4.0f * dm * dm;                  // exact max of the 10 logits
    float se = 0.0f, nc = 0.0f, n0 = 0.0f;
    #pragma unroll
    for (int q = 0; q < 10; q++) {
        float t = raw - (float)q;
        float e = __expf(fmaf(-4.0f * t, t, -m));
        se += e;
        nc = fmaf(e, P[80 + q], nc);
        n0 = fmaf(e, P[96 + q], n0);
    }
    float inv = 1.0f / se;
    float out0  = nc * inv * (1.0f / 9.0f);
    float out15 = 1.0f - n0 * inv;

    float4 W0 = make_float4(out0, y1,  y2,  y3);
    float4 W1 = make_float4(y4,   y5,  y6,  y7);
    float4 W2 = make_float4(y8,   y9,  y10, y11);
    float4 W3 = make_float4(y12,  y13, y14, out15);

    // 4x4 register transpose across the 4-lane group: O_c[k] = W_k[c]
    {   // stage 1 (xor 1): lane sends slot 2j+(1-c0), stores received there
        bool odd = (c & 1);
        float4 s0 = odd ? W0 : W1;
        float4 r0 = shfl_xor4(s0, 1);
        W0 = odd ? r0 : W0;
        W1 = odd ? W1 : r0;
        float4 s1 = odd ? W2 : W3;
        float4 r1 = shfl_xor4(s1, 1);
        W2 = odd ? r1 : W2;
        W3 = odd ? W3 : r1;
    }
    {   // stage 2 (xor 2): lane sends slot (1-c1)*2+j
        bool hi = (c & 2);
        float4 s0 = hi ? W0 : W2;
        float4 r0 = shfl_xor4(s0, 2);
        W0 = hi ? r0 : W0;
        W2 = hi ? W2 : r0;
        float4 s1 = hi ? W1 : W3;
        float4 r1 = shfl_xor4(s1, 2);
        W1 = hi ? r1 : W1;
        W3 = hi ? W3 : r1;
    }

    // coalesced streaming stores: element k*256+tid = row k*64+i, quarter c
    if (0 * 64 + i < nvalid) __stcs(gout + 0 * 256 + tid, W0);
    if (1 * 64 + i < nvalid) __stcs(gout + 1 * 256 + tid, W1);
    if (2 * 64 + i < nvalid) __stcs(gout + 2 * 256 + tid, W2);
    if (3 * 64 + i < nvalid) __stcs(gout + 3 * 256 + tid, W3);
}

extern "C" void kernel_launch(void* const* d_in, const int* in_sizes, int n_in,
                              void* d_out, int out_size)
{
    const float* state = (const float*)d_in[0];
    const float* instr = (const float*)d_in[1];
    const float* remap = (const float*)d_in[2];
    const float* selw  = (const float*)d_in[3];
    const float* selb  = (const float*)d_in[4];
    float* out = (float*)d_out;

    const int B = in_sizes[1] / DMV;            // 32
    const int N = in_sizes[0] / in_sizes[1];    // 100000

    setup_kernel<<<1, 1024>>>(instr, remap, selw, selb);

    dim3 grid((N + TILE - 1) / TILE, B);
    sandwich_color_kernel<<<grid, 256>>>(state, out, N);
}